// round 7
// baseline (speedup 1.0000x reference)
#include <cuda_runtime.h>
#include <cstdint>
#include <cstddef>

// Problem constants
#define BB   32
#define TT   1024
#define CC   512
#define KK   3
#define LMAX 4096
#define BT   (BB*TT)
#define LN_EPS 1e-5f

// GEMM tiling (tf32 mma.sync m16n8k8)
#define BM 128
#define BN 128
#define BK 16
#define NSLAB ((KK*CC)/BK)    // 96
#define STG 3

// k-pair permutation within each 8-group: physical[2t]=logical[t], physical[2t+1]=logical[t+4]
__host__ __device__ __forceinline__ int kperm(int j) {
    return (j < 4) ? 2 * j : 2 * (j - 4) + 1;
}

// ---------------- scratch (device globals; no allocations allowed) ----------
__device__ float g_bufA[(size_t)BT * CC];          // tf32-rounded + k-permuted batch
__device__ float g_buf1[(size_t)BT * CC];          // conv1 out (normal) -> ln -> permuted
__device__ float g_buf2[(size_t)BT * CC];
__device__ float g_wt[2 * KK * CC * CC];           // [set][k][ci/8][co][8perm]
__device__ int   g_cum[BB * TT];

// ================= helpers ==================================================
__device__ __forceinline__ uint32_t smem_u32(const void* p) {
    uint32_t r;
    asm("{ .reg .u64 t; cvta.to.shared.u64 t, %1; cvt.u32.u64 %0, t; }"
        : "=r"(r) : "l"(p));
    return r;
}
__device__ __forceinline__ void cp_async16(uint32_t dst, const void* src, bool ok) {
    int sz = ok ? 16 : 0;
    asm volatile("cp.async.ca.shared.global [%0], [%1], 16, %2;"
                 :: "r"(dst), "l"(src), "r"(sz));
}
#define CP_COMMIT() asm volatile("cp.async.commit_group;" ::: "memory")
#define CP_WAIT1()  asm volatile("cp.async.wait_group 1;" ::: "memory")

__device__ __forceinline__ float f_rna_tf32(float f) {
    uint32_t u;
    asm("cvt.rna.tf32.f32 %0, %1;" : "=r"(u) : "f"(f));
    return __uint_as_float(u);
}
__device__ __forceinline__ void mma_tf32(float* c, const uint32_t* a, const uint32_t* b) {
    asm volatile("mma.sync.aligned.m16n8k8.row.col.f32.tf32.tf32.f32 "
                 "{%0,%1,%2,%3}, {%4,%5,%6,%7}, {%8,%9}, {%0,%1,%2,%3};"
                 : "+f"(c[0]), "+f"(c[1]), "+f"(c[2]), "+f"(c[3])
                 : "r"(a[0]), "r"(a[1]), "r"(a[2]), "r"(a[3]),
                   "r"(b[0]), "r"(b[1]));
}

// ---------------- tf32 pre-round + k-permute copy (batch -> g_bufA) ---------
__global__ void __launch_bounds__(256) round_kernel(const float4* __restrict__ in,
                                                    float* __restrict__ out)
{
    size_t i = (size_t)blockIdx.x * 256 + threadIdx.x;   // over BT*CC/4
    float4 v = in[i];
    size_t base = (i >> 1) * 8;        // 8-group base
    int half = (int)(i & 1);           // logical j = half*4 + t  -> pos = 2*t + half
    out[base + 0 + half] = f_rna_tf32(v.x);
    out[base + 2 + half] = f_rna_tf32(v.y);
    out[base + 4 + half] = f_rna_tf32(v.z);
    out[base + 6 + half] = f_rna_tf32(v.w);
}

// ---- weight transform: w[co][ci][k] -> wt[k][ci/8][co][kperm(ci%8)], tf32 --
__global__ void __launch_bounds__(256) wt_kernel(const float* __restrict__ w,
                                                 float* __restrict__ wt)
{
    int idx = blockIdx.x * 256 + threadIdx.x;
    if (idx >= CC * CC) return;
    int co = idx >> 9;
    int ci = idx & (CC - 1);
    int gg = ci >> 3;
    int p  = kperm(ci & 7);
#pragma unroll
    for (int k = 0; k < KK; k++)
        wt[(((size_t)k * 64 + gg) * CC + co) * 8 + p] =
            f_rna_tf32(w[((size_t)co * CC + ci) * KK + k]);
}

// ---------------- durations: mask, total==0 fallback, inclusive scan --------
__global__ void __launch_bounds__(256) dur_kernel(const int* __restrict__ durs,
                                                  const int* __restrict__ lens,
                                                  int* __restrict__ cum,
                                                  float* __restrict__ mel)
{
    int b   = blockIdx.x;
    int len = lens[b];
    int tid = threadIdx.x;
    int base = tid * 4;
    const int* drow = durs + (size_t)b * TT;

    int d[4];
#pragma unroll
    for (int j = 0; j < 4; j++)
        d[j] = (base + j < len) ? drow[base + j] : 0;
    int ls = d[0] + d[1] + d[2] + d[3];

    __shared__ int sred[256];
    sred[tid] = ls;
    __syncthreads();
    for (int o = 128; o > 0; o >>= 1) {
        if (tid < o) sred[tid] += sred[tid + o];
        __syncthreads();
    }
    int total = sred[0];
    __syncthreads();

    if (total == 0) {
#pragma unroll
        for (int j = 0; j < 4; j++)
            d[j] = (base + j < len) ? 1 : 0;
        ls = d[0] + d[1] + d[2] + d[3];
    }

    __shared__ int sscan[256];
    sscan[tid] = ls;
    __syncthreads();
    for (int o = 1; o < 256; o <<= 1) {
        int v = (tid >= o) ? sscan[tid - o] : 0;
        __syncthreads();
        sscan[tid] += v;
        __syncthreads();
    }
    int c = sscan[tid] - ls;
#pragma unroll
    for (int j = 0; j < 4; j++) {
        c += d[j];
        cum[(size_t)b * TT + base + j] = c;
    }
    if (tid == 255) mel[b] = (float)c;
}

// ---------------- conv-as-GEMM on tf32 mma.sync (permuted operands) ---------
// out[m,n] = relu(sum_k sum_ci A[m+k-1,ci] * W[k][ci][n] + bias[n])
__global__ void __launch_bounds__(256, 2) conv_mma_kernel(const float* __restrict__ A,
                                                          const float* __restrict__ Wt,
                                                          const float* __restrict__ bias,
                                                          float* __restrict__ out)
{
    __shared__ float As[STG][2][BM][8];    // 24576 B
    __shared__ float Bs[STG][2][BN][8];    // 24576 B

    int tid  = threadIdx.x;
    int wid  = tid >> 5;
    int lane = tid & 31;
    int warp_m = wid & 1;        // 2 warps in M (64 rows each)
    int warp_n = wid >> 1;       // 4 warps in N (32 cols each)
    int gid = lane >> 2;         // 0..7
    int tig = lane & 3;          // 0..3

    int m0 = blockIdx.x * BM;
    int b  = m0 >> 10;
    int t0 = m0 & 1023;
    int n0 = blockIdx.y * BN;
    const float* Ab = A + (size_t)b * TT * CC;

    // loader: 16B chunk per (row, half); both groups per thread
    int lrow  = tid >> 1;        // 0..127
    int lhalf = tid & 1;         // 0/1

    float c[4][4][4];
#pragma unroll
    for (int mt = 0; mt < 4; mt++)
#pragma unroll
        for (int nt = 0; nt < 4; nt++)
#pragma unroll
            for (int q = 0; q < 4; q++) c[mt][nt][q] = 0.f;

    auto load_slab = [&](int s, int st) {
        int k   = s >> 5;              // conv tap 0..2
        int ci0 = (s & 31) * BK;       // 0..496 (physical == logical group base)
        int g0  = (s & 31) * 2;        // global 8-group index base
        int strow = t0 + lrow + k - 1;
        bool ok = (strow >= 0 && strow < TT);
        const float* asrc = Ab + (ok ? (size_t)strow * CC : 0) + ci0 + lhalf * 4;
        cp_async16(smem_u32(&As[st][0][lrow][lhalf * 4]), asrc, ok);
        cp_async16(smem_u32(&As[st][1][lrow][lhalf * 4]), asrc + 8, ok);
        const float* bsrc = Wt + (((size_t)k * 64 + g0) * CC + n0 + lrow) * 8 + lhalf * 4;
        cp_async16(smem_u32(&Bs[st][0][lrow][lhalf * 4]), bsrc, true);
        cp_async16(smem_u32(&Bs[st][1][lrow][lhalf * 4]), bsrc + CC * 8, true);
    };

    load_slab(0, 0); CP_COMMIT();
    load_slab(1, 1); CP_COMMIT();

    for (int s = 0; s < NSLAB; s++) {
        int st = s % STG;
        CP_WAIT1();                       // slab s resident
        __syncthreads();                  // also: stage (s+2)%STG fully consumed
        if (s + 2 < NSLAB) load_slab(s + 2, (s + 2) % STG);
        CP_COMMIT();                      // empty group at tail keeps wait semantics

#pragma unroll
        for (int g = 0; g < 2; g++) {
            uint32_t af[4][4];
#pragma unroll
            for (int mt = 0; mt < 4; mt++) {
                int mr = warp_m * 64 + mt * 16;
                float2 p = *(const float2*)&As[st][g][mr + gid    ][tig * 2];
                float2 q = *(const float2*)&As[st][g][mr + gid + 8][tig * 2];
                af[mt][0] = __float_as_uint(p.x);
                af[mt][2] = __float_as_uint(p.y);
                af[mt][1] = __float_as_uint(q.x);
                af[mt][3] = __float_as_uint(q.y);
            }
            uint32_t bf[4][2];
#pragma unroll
            for (int nt = 0; nt < 4; nt++) {
                int nc = warp_n * 32 + nt * 8 + gid;
                float2 r = *(const float2*)&Bs[st][g][nc][tig * 2];
                bf[nt][0] = __float_as_uint(r.x);
                bf[nt][1] = __float_as_uint(r.y);
            }
#pragma unroll
            for (int mt = 0; mt < 4; mt++)
#pragma unroll
                for (int nt = 0; nt < 4; nt++)
                    mma_tf32(c[mt][nt], af[mt], bf[nt]);
        }
    }

    // ---- epilogue: bias + relu, coalesced-quad stores (normal co order) ----
#pragma unroll
    for (int mt = 0; mt < 4; mt++) {
        int row = m0 + warp_m * 64 + mt * 16 + gid;
#pragma unroll
        for (int nt = 0; nt < 4; nt++) {
            int col = n0 + warp_n * 32 + nt * 8 + tig * 2;
            float b0 = __ldg(&bias[col]);
            float b1 = __ldg(&bias[col + 1]);
            float2 v0, v1;
            v0.x = fmaxf(c[mt][nt][0] + b0, 0.f);
            v0.y = fmaxf(c[mt][nt][1] + b1, 0.f);
            v1.x = fmaxf(c[mt][nt][2] + b0, 0.f);
            v1.y = fmaxf(c[mt][nt][3] + b1, 0.f);
            *(float2*)&out[(size_t)row * CC + col]       = v0;
            *(float2*)&out[(size_t)(row + 8) * CC + col] = v1;
        }
    }
}

// ---------------- LayerNorm over C=512, one block per row -------------------
// Reads normal order, writes tf32-rounded + k-permuted (input to conv2).
__global__ void __launch_bounds__(128) ln_kernel(float* __restrict__ x,
                                                 const float* __restrict__ g,
                                                 const float* __restrict__ beta)
{
    size_t row = blockIdx.x;
    float* xrow = x + row * CC;
    int tid = threadIdx.x;
    float4 v = ((const float4*)xrow)[tid];
    float s = v.x + v.y + v.z + v.w;
    float q = v.x * v.x + v.y * v.y + v.z * v.z + v.w * v.w;
#pragma unroll
    for (int o = 16; o > 0; o >>= 1) {
        s += __shfl_xor_sync(0xffffffffu, s, o);
        q += __shfl_xor_sync(0xffffffffu, q, o);
    }
    __shared__ float ss[4], sq[4];
    int w = tid >> 5, l = tid & 31;
    if (l == 0) { ss[w] = s; sq[w] = q; }
    __syncthreads();
    s = ss[0] + ss[1] + ss[2] + ss[3];
    q = sq[0] + sq[1] + sq[2] + sq[3];
    float mean = s * (1.f / CC);
    float var  = q * (1.f / CC) - mean * mean;
    float r = rsqrtf(var + LN_EPS);
    float4 gv = ((const float4*)g)[tid];
    float4 bv = ((const float4*)beta)[tid];
    float o0 = f_rna_tf32((v.x - mean) * r * gv.x + bv.x);
    float o1 = f_rna_tf32((v.y - mean) * r * gv.y + bv.y);
    float o2 = f_rna_tf32((v.z - mean) * r * gv.z + bv.z);
    float o3 = f_rna_tf32((v.w - mean) * r * gv.w + bv.w);
    __syncthreads();     // all reads of this row done before permuted overwrite
    int base = (tid >> 1) * 8;
    int half = tid & 1;
    xrow[base + 0 + half] = o0;
    xrow[base + 2 + half] = o1;
    xrow[base + 4 + half] = o2;
    xrow[base + 6 + half] = o3;
}

// ---------------- LN + Linear(C->1) + mask, one block per row ---------------
__global__ void __launch_bounds__(128) ln_lin_kernel(const float* __restrict__ x,
                                                     const float* __restrict__ g,
                                                     const float* __restrict__ beta,
                                                     const float* __restrict__ lw,
                                                     const float* __restrict__ lb,
                                                     const int* __restrict__ lens,
                                                     float* __restrict__ pred)
{
    size_t row = blockIdx.x;
    const float4* xr = (const float4*)(x + row * CC);
    int tid = threadIdx.x;
    float4 v = xr[tid];
    float s = v.x + v.y + v.z + v.w;
    float q = v.x * v.x + v.y * v.y + v.z * v.z + v.w * v.w;
#pragma unroll
    for (int o = 16; o > 0; o >>= 1) {
        s += __shfl_xor_sync(0xffffffffu, s, o);
        q += __shfl_xor_sync(0xffffffffu, q, o);
    }
    __shared__ float ss[4], sq[4], sp[4];
    int w = tid >> 5, l = tid & 31;
    if (l == 0) { ss[w] = s; sq[w] = q; }
    __syncthreads();
    s = ss[0] + ss[1] + ss[2] + ss[3];
    q = sq[0] + sq[1] + sq[2] + sq[3];
    float mean = s * (1.f / CC);
    float var  = q * (1.f / CC) - mean * mean;
    float r = rsqrtf(var + LN_EPS);
    float4 gv = ((const float4*)g)[tid];
    float4 bv = ((const float4*)beta)[tid];
    float4 wv = ((const float4*)lw)[tid];
    float part = ((v.x - mean) * r * gv.x + bv.x) * wv.x
               + ((v.y - mean) * r * gv.y + bv.y) * wv.y
               + ((v.z - mean) * r * gv.z + bv.z) * wv.z
               + ((v.w - mean) * r * gv.w + bv.w) * wv.w;
#pragma unroll
    for (int o = 16; o > 0; o >>= 1)
        part += __shfl_xor_sync(0xffffffffu, part, o);
    if (l == 0) sp[w] = part;
    __syncthreads();
    if (tid == 0) {
        float val = sp[0] + sp[1] + sp[2] + sp[3] + lb[0];
        int b = (int)(row >> 10);
        int t = (int)(row & 1023);
        pred[row] = (t < lens[b]) ? val : 0.f;
    }
}

// ---------------- regulate: per-frame binary search + row copy --------------
__global__ void __launch_bounds__(256) reg_kernel(const float* __restrict__ batch,
                                                  const int* __restrict__ cum,
                                                  float* __restrict__ out)
{
    int b  = blockIdx.y;
    int f0 = blockIdx.x * 32;
    __shared__ int sc[TT];
    int tid = threadIdx.x;
    const int* crow = cum + (size_t)b * TT;
#pragma unroll
    for (int j = 0; j < 4; j++) sc[tid + 256 * j] = crow[tid + 256 * j];
    __syncthreads();
    int total = sc[TT - 1];
    int warp = tid >> 5, lane = tid & 31;
    float* outb = out + (size_t)b * LMAX * CC;
    const float* inb = batch + (size_t)b * TT * CC;
#pragma unroll
    for (int qq = 0; qq < 4; qq++) {
        int f = f0 + warp * 4 + qq;
        float4* dst = (float4*)(outb + (size_t)f * CC);
        if (f < total) {
            int lo = 0, hi = TT;
            while (lo < hi) {
                int mid = (lo + hi) >> 1;
                if (sc[mid] <= f) lo = mid + 1; else hi = mid;
            }
            const float4* src = (const float4*)(inb + (size_t)lo * CC);
#pragma unroll
            for (int u = 0; u < 4; u++) dst[lane + 32 * u] = src[lane + 32 * u];
        } else {
            float4 z = make_float4(0.f, 0.f, 0.f, 0.f);
#pragma unroll
            for (int u = 0; u < 4; u++) dst[lane + 32 * u] = z;
        }
    }
}

// ---------------- launch --------------------------------------------------
extern "C" void kernel_launch(void* const* d_in, const int* in_sizes, int n_in,
                              void* d_out, int out_size)
{
    const float* batch = (const float*)d_in[0];
    const int*   lens  = (const int*)d_in[1];
    const int*   durs  = (const int*)d_in[3];
    const float* w1    = (const float*)d_in[4];
    const float* b1    = (const float*)d_in[5];
    const float* g1    = (const float*)d_in[6];
    const float* be1   = (const float*)d_in[7];
    const float* w2    = (const float*)d_in[8];
    const float* b2    = (const float*)d_in[9];
    const float* g2    = (const float*)d_in[10];
    const float* be2   = (const float*)d_in[11];
    const float* lw    = (const float*)d_in[12];
    const float* lb    = (const float*)d_in[13];

    float* out    = (float*)d_out;
    float* padded = out;
    float* mel    = out + (size_t)BB * LMAX * CC;
    float* pred   = mel + BB;

    float *bufA, *buf1, *buf2, *wt;
    int   *cum;
    cudaGetSymbolAddress((void**)&bufA, g_bufA);
    cudaGetSymbolAddress((void**)&buf1, g_buf1);
    cudaGetSymbolAddress((void**)&buf2, g_buf2);
    cudaGetSymbolAddress((void**)&wt,   g_wt);
    cudaGetSymbolAddress((void**)&cum,  g_cum);
    float* wt2 = wt + (size_t)KK * CC * CC;

    wt_kernel<<<(CC * CC + 255) / 256, 256>>>(w1, wt);
    wt_kernel<<<(CC * CC + 255) / 256, 256>>>(w2, wt2);
    dur_kernel<<<BB, 256>>>(durs, lens, cum, mel);
    round_kernel<<<(BT * (CC / 4)) / 256, 256>>>((const float4*)batch, bufA);

    dim3 gg(BT / BM, CC / BN);
    conv_mma_kernel<<<gg, 256>>>(bufA, wt, b1, buf1);
    ln_kernel<<<BT, 128>>>(buf1, g1, be1);
    conv_mma_kernel<<<gg, 256>>>(buf1, wt2, b2, buf2);
    ln_lin_kernel<<<BT, 128>>>(buf2, g2, be2, lw, lb, lens, pred);

    reg_kernel<<<dim3(LMAX / 32, BB), 256>>>(batch, cum, padded);
}

// round 8
// speedup vs baseline: 1.7265x; 1.7265x over previous
#include <cuda_runtime.h>
#include <cuda_fp16.h>
#include <cstdint>
#include <cstddef>

// Problem constants
#define BB   32
#define TT   1024
#define CC   512
#define KK   3
#define LMAX 4096
#define BT   (BB*TT)
#define LN_EPS 1e-5f

// GEMM tiling (fp16 mma.sync m16n8k16, fp32 accumulate)
#define BM 128
#define BN 128
#define BK 16
#define NSLAB ((KK*CC)/BK)    // 96
#define STG 3

// pair permutation within each 16-k group: pair t -> slot (t<4 ? 2t : 2(t-4)+1)
// => LDS.64 at halfoff tig*4 yields {pair tig, pair tig+4} = {k2tig,k2tig+1, k2tig+8,k2tig+9}
__host__ __device__ __forceinline__ int pslot(int t) {
    return (t < 4) ? 2 * t : 2 * (t - 4) + 1;
}

// ---------------- scratch (device globals; no allocations allowed) ----------
__device__ __half g_bufA[(size_t)BT * CC];         // fp16 pair-permuted batch
__device__ float  g_buf1[(size_t)BT * CC];         // conv1 out fp32 (normal order)
__device__ __half g_buf1h[(size_t)BT * CC];        // ln(conv1) fp16 pair-permuted
__device__ float  g_buf2[(size_t)BT * CC];         // conv2 out fp32
__device__ __half g_wt[2 * (size_t)KK * CC * CC];  // [set][k][ci/16][co][16perm]
__device__ int    g_cum[BB * TT];

// ================= helpers ==================================================
__device__ __forceinline__ uint32_t smem_u32(const void* p) {
    uint32_t r;
    asm("{ .reg .u64 t; cvta.to.shared.u64 t, %1; cvt.u32.u64 %0, t; }"
        : "=r"(r) : "l"(p));
    return r;
}
__device__ __forceinline__ void cp_async16(uint32_t dst, const void* src, bool ok) {
    int sz = ok ? 16 : 0;
    asm volatile("cp.async.ca.shared.global [%0], [%1], 16, %2;"
                 :: "r"(dst), "l"(src), "r"(sz));
}
#define CP_COMMIT() asm volatile("cp.async.commit_group;" ::: "memory")
#define CP_WAIT1()  asm volatile("cp.async.wait_group 1;" ::: "memory")

__device__ __forceinline__ void mma_f16(float* c, const uint32_t* a, const uint32_t* b) {
    asm volatile("mma.sync.aligned.m16n8k16.row.col.f32.f16.f16.f32 "
                 "{%0,%1,%2,%3}, {%4,%5,%6,%7}, {%8,%9}, {%0,%1,%2,%3};"
                 : "+f"(c[0]), "+f"(c[1]), "+f"(c[2]), "+f"(c[3])
                 : "r"(a[0]), "r"(a[1]), "r"(a[2]), "r"(a[3]),
                   "r"(b[0]), "r"(b[1]));
}

// write 4 consecutive logical values (w = within-group start, multiple of 4)
// into pair-permuted fp16 group storage.
__device__ __forceinline__ void store_perm4(__half* gbase, int w,
                                            float v0, float v1, float v2, float v3)
{
    int t0 = w >> 1;             // pair index of (v0,v1)
    int s0 = pslot(t0);
    int s1 = pslot(t0 + 1);
    *(__half2*)(gbase + s0 * 2) = __floats2half2_rn(v0, v1);
    *(__half2*)(gbase + s1 * 2) = __floats2half2_rn(v2, v3);
}

// ---------------- fp16 pre-round + pair-permute copy (batch -> g_bufA) ------
__global__ void __launch_bounds__(256) round_kernel(const float4* __restrict__ in,
                                                    __half* __restrict__ out)
{
    size_t i = (size_t)blockIdx.x * 256 + threadIdx.x;   // over BT*CC/4
    float4 v = in[i];
    int f = (int)(i & 127);            // float4 index within row (CC/4 = 128)
    size_t rowbase = (i >> 7) * CC;
    int g = f >> 2;                    // 16-element group
    int w = (f & 3) * 4;               // within-group start
    store_perm4(out + rowbase + g * 16, w, v.x, v.y, v.z, v.w);
}

// ---- weight transform: w[co][ci][k] -> wt[k][ci/16][co][pslot perm], fp16 --
__global__ void __launch_bounds__(256) wt_kernel(const float* __restrict__ w,
                                                 __half* __restrict__ wt)
{
    int idx = blockIdx.x * 256 + threadIdx.x;
    if (idx >= CC * CC) return;
    int co = idx >> 9;
    int ci = idx & (CC - 1);
    int g  = ci >> 4;
    int w16 = ci & 15;
    int pos = pslot(w16 >> 1) * 2 + (w16 & 1);
#pragma unroll
    for (int k = 0; k < KK; k++)
        wt[(((size_t)k * 32 + g) * CC + co) * 16 + pos] =
            __float2half_rn(w[((size_t)co * CC + ci) * KK + k]);
}

// ---------------- durations: mask, total==0 fallback, inclusive scan --------
__global__ void __launch_bounds__(256) dur_kernel(const int* __restrict__ durs,
                                                  const int* __restrict__ lens,
                                                  int* __restrict__ cum,
                                                  float* __restrict__ mel)
{
    int b   = blockIdx.x;
    int len = lens[b];
    int tid = threadIdx.x;
    int base = tid * 4;
    const int* drow = durs + (size_t)b * TT;

    int d[4];
#pragma unroll
    for (int j = 0; j < 4; j++)
        d[j] = (base + j < len) ? drow[base + j] : 0;
    int ls = d[0] + d[1] + d[2] + d[3];

    __shared__ int sred[256];
    sred[tid] = ls;
    __syncthreads();
    for (int o = 128; o > 0; o >>= 1) {
        if (tid < o) sred[tid] += sred[tid + o];
        __syncthreads();
    }
    int total = sred[0];
    __syncthreads();

    if (total == 0) {
#pragma unroll
        for (int j = 0; j < 4; j++)
            d[j] = (base + j < len) ? 1 : 0;
        ls = d[0] + d[1] + d[2] + d[3];
    }

    __shared__ int sscan[256];
    sscan[tid] = ls;
    __syncthreads();
    for (int o = 1; o < 256; o <<= 1) {
        int v = (tid >= o) ? sscan[tid - o] : 0;
        __syncthreads();
        sscan[tid] += v;
        __syncthreads();
    }
    int c = sscan[tid] - ls;
#pragma unroll
    for (int j = 0; j < 4; j++) {
        c += d[j];
        cum[(size_t)b * TT + base + j] = c;
    }
    if (tid == 255) mel[b] = (float)c;
}

// ---------------- conv-as-GEMM on fp16 mma.sync (permuted operands) ---------
// out[m,n] = relu(sum_k sum_ci A[m+k-1,ci] * W[k][ci][n] + bias[n])
__global__ void __launch_bounds__(256, 2) conv_mma_kernel(const __half* __restrict__ A,
                                                          const __half* __restrict__ Wt,
                                                          const float* __restrict__ bias,
                                                          float* __restrict__ out)
{
    __shared__ __align__(16) __half As[STG][BM][16];   // 4KB/stage
    __shared__ __align__(16) __half Bs[STG][BN][16];   // 4KB/stage

    int tid  = threadIdx.x;
    int wid  = tid >> 5;
    int lane = tid & 31;
    int warp_m = wid & 1;        // 2 warps in M (64 rows each)
    int warp_n = wid >> 1;       // 4 warps in N (32 cols each)
    int gid = lane >> 2;         // 0..7
    int tig = lane & 3;          // 0..3

    int m0 = blockIdx.x * BM;
    int b  = m0 >> 10;
    int t0 = m0 & 1023;
    int n0 = blockIdx.y * BN;
    const __half* Ab = A + (size_t)b * TT * CC;

    // loader: thread -> one 16B A chunk + one 16B B chunk
    int lrow  = tid >> 1;        // 0..127
    int lhalf = tid & 1;         // 0/1 (8 halves each)

    float c[4][4][4];
#pragma unroll
    for (int mt = 0; mt < 4; mt++)
#pragma unroll
        for (int nt = 0; nt < 4; nt++)
#pragma unroll
            for (int q = 0; q < 4; q++) c[mt][nt][q] = 0.f;

    auto load_slab = [&](int s, int st) {
        int k  = s >> 5;               // conv tap 0..2
        int gI = s & 31;               // ci 16-group index
        int strow = t0 + lrow + k - 1;
        bool ok = (strow >= 0 && strow < TT);
        const __half* asrc = Ab + (ok ? (size_t)strow * CC : 0) + gI * 16 + lhalf * 8;
        cp_async16(smem_u32(&As[st][lrow][lhalf * 8]), asrc, ok);
        const __half* bsrc = Wt + (((size_t)k * 32 + gI) * CC + n0 + lrow) * 16 + lhalf * 8;
        cp_async16(smem_u32(&Bs[st][lrow][lhalf * 8]), bsrc, true);
    };

    load_slab(0, 0); CP_COMMIT();
    load_slab(1, 1); CP_COMMIT();

    for (int s = 0; s < NSLAB; s++) {
        int st = s % STG;
        CP_WAIT1();                       // slab s resident
        __syncthreads();                  // also: stage (s+2)%STG fully consumed
        if (s + 2 < NSLAB) load_slab(s + 2, (s + 2) % STG);
        CP_COMMIT();                      // empty group at tail keeps wait semantics

        uint32_t af[4][4];
#pragma unroll
        for (int mt = 0; mt < 4; mt++) {
            int mr = warp_m * 64 + mt * 16;
            uint2 lo = *(const uint2*)&As[st][mr + gid    ][tig * 4];
            uint2 hi = *(const uint2*)&As[st][mr + gid + 8][tig * 4];
            af[mt][0] = lo.x;   // rows gid,   k 2tig..2tig+1
            af[mt][2] = lo.y;   // rows gid,   k 2tig+8..+9
            af[mt][1] = hi.x;   // rows gid+8, k low
            af[mt][3] = hi.y;   // rows gid+8, k high
        }
        uint32_t bf[4][2];
#pragma unroll
        for (int nt = 0; nt < 4; nt++) {
            int nc = warp_n * 32 + nt * 8 + gid;
            uint2 r = *(const uint2*)&Bs[st][nc][tig * 4];
            bf[nt][0] = r.x;
            bf[nt][1] = r.y;
        }
#pragma unroll
        for (int mt = 0; mt < 4; mt++)
#pragma unroll
            for (int nt = 0; nt < 4; nt++)
                mma_f16(c[mt][nt], af[mt], bf[nt]);
    }

    // ---- epilogue: bias + relu, coalesced-quad stores ----
#pragma unroll
    for (int mt = 0; mt < 4; mt++) {
        int row = m0 + warp_m * 64 + mt * 16 + gid;
#pragma unroll
        for (int nt = 0; nt < 4; nt++) {
            int col = n0 + warp_n * 32 + nt * 8 + tig * 2;
            float b0 = __ldg(&bias[col]);
            float b1 = __ldg(&bias[col + 1]);
            float2 v0, v1;
            v0.x = fmaxf(c[mt][nt][0] + b0, 0.f);
            v0.y = fmaxf(c[mt][nt][1] + b1, 0.f);
            v1.x = fmaxf(c[mt][nt][2] + b0, 0.f);
            v1.y = fmaxf(c[mt][nt][3] + b1, 0.f);
            *(float2*)&out[(size_t)row * CC + col]       = v0;
            *(float2*)&out[(size_t)(row + 8) * CC + col] = v1;
        }
    }
}

// ---------------- LayerNorm over C=512, one block per row -------------------
// Reads fp32 normal order, writes fp16 pair-permuted (input to conv2).
__global__ void __launch_bounds__(128) ln_kernel(const float* __restrict__ x,
                                                 const float* __restrict__ g,
                                                 const float* __restrict__ beta,
                                                 __half* __restrict__ xo)
{
    size_t row = blockIdx.x;
    const float4* xr = (const float4*)(x + row * CC);
    int tid = threadIdx.x;
    float4 v = xr[tid];
    float s = v.x + v.y + v.z + v.w;
    float q = v.x * v.x + v.y * v.y + v.z * v.z + v.w * v.w;
#pragma unroll
    for (int o = 16; o > 0; o >>= 1) {
        s += __shfl_xor_sync(0xffffffffu, s, o);
        q += __shfl_xor_sync(0xffffffffu, q, o);
    }
    __shared__ float ss[4], sq[4];
    int w = tid >> 5, l = tid & 31;
    if (l == 0) { ss[w] = s; sq[w] = q; }
    __syncthreads();
    s = ss[0] + ss[1] + ss[2] + ss[3];
    q = sq[0] + sq[1] + sq[2] + sq[3];
    float mean = s * (1.f / CC);
    float var  = q * (1.f / CC) - mean * mean;
    float r = rsqrtf(var + LN_EPS);
    float4 gv = ((const float4*)g)[tid];
    float4 bv = ((const float4*)beta)[tid];
    float o0 = (v.x - mean) * r * gv.x + bv.x;
    float o1 = (v.y - mean) * r * gv.y + bv.y;
    float o2 = (v.z - mean) * r * gv.z + bv.z;
    float o3 = (v.w - mean) * r * gv.w + bv.w;
    int grp = tid >> 2;
    int wof = (tid & 3) * 4;
    store_perm4(xo + row * CC + grp * 16, wof, o0, o1, o2, o3);
}

// ---------------- LN + Linear(C->1) + mask, one block per row ---------------
__global__ void __launch_bounds__(128) ln_lin_kernel(const float* __restrict__ x,
                                                     const float* __restrict__ g,
                                                     const float* __restrict__ beta,
                                                     const float* __restrict__ lw,
                                                     const float* __restrict__ lb,
                                                     const int* __restrict__ lens,
                                                     float* __restrict__ pred)
{
    size_t row = blockIdx.x;
    const float4* xr = (const float4*)(x + row * CC);
    int tid = threadIdx.x;
    float4 v = xr[tid];
    float s = v.x + v.y + v.z + v.w;
    float q = v.x * v.x + v.y * v.y + v.z * v.z + v.w * v.w;
#pragma unroll
    for (int o = 16; o > 0; o >>= 1) {
        s += __shfl_xor_sync(0xffffffffu, s, o);
        q += __shfl_xor_sync(0xffffffffu, q, o);
    }
    __shared__ float ss[4], sq[4], sp[4];
    int w = tid >> 5, l = tid & 31;
    if (l == 0) { ss[w] = s; sq[w] = q; }
    __syncthreads();
    s = ss[0] + ss[1] + ss[2] + ss[3];
    q = sq[0] + sq[1] + sq[2] + sq[3];
    float mean = s * (1.f / CC);
    float var  = q * (1.f / CC) - mean * mean;
    float r = rsqrtf(var + LN_EPS);
    float4 gv = ((const float4*)g)[tid];
    float4 bv = ((const float4*)beta)[tid];
    float4 wv = ((const float4*)lw)[tid];
    float part = ((v.x - mean) * r * gv.x + bv.x) * wv.x
               + ((v.y - mean) * r * gv.y + bv.y) * wv.y
               + ((v.z - mean) * r * gv.z + bv.z) * wv.z
               + ((v.w - mean) * r * gv.w + bv.w) * wv.w;
#pragma unroll
    for (int o = 16; o > 0; o >>= 1)
        part += __shfl_xor_sync(0xffffffffu, part, o);
    if (l == 0) sp[w] = part;
    __syncthreads();
    if (tid == 0) {
        float val = sp[0] + sp[1] + sp[2] + sp[3] + lb[0];
        int b = (int)(row >> 10);
        int t = (int)(row & 1023);
        pred[row] = (t < lens[b]) ? val : 0.f;
    }
}

// ---------------- regulate: per-frame binary search + row copy --------------
__global__ void __launch_bounds__(256) reg_kernel(const float* __restrict__ batch,
                                                  const int* __restrict__ cum,
                                                  float* __restrict__ out)
{
    int b  = blockIdx.y;
    int f0 = blockIdx.x * 32;
    __shared__ int sc[TT];
    int tid = threadIdx.x;
    const int* crow = cum + (size_t)b * TT;
#pragma unroll
    for (int j = 0; j < 4; j++) sc[tid + 256 * j] = crow[tid + 256 * j];
    __syncthreads();
    int total = sc[TT - 1];
    int warp = tid >> 5, lane = tid & 31;
    float* outb = out + (size_t)b * LMAX * CC;
    const float* inb = batch + (size_t)b * TT * CC;
#pragma unroll
    for (int qq = 0; qq < 4; qq++) {
        int f = f0 + warp * 4 + qq;
        float4* dst = (float4*)(outb + (size_t)f * CC);
        if (f < total) {
            int lo = 0, hi = TT;
            while (lo < hi) {
                int mid = (lo + hi) >> 1;
                if (sc[mid] <= f) lo = mid + 1; else hi = mid;
            }
            const float4* src = (const float4*)(inb + (size_t)lo * CC);
#pragma unroll
            for (int u = 0; u < 4; u++) dst[lane + 32 * u] = src[lane + 32 * u];
        } else {
            float4 z = make_float4(0.f, 0.f, 0.f, 0.f);
#pragma unroll
            for (int u = 0; u < 4; u++) dst[lane + 32 * u] = z;
        }
    }
}

// ---------------- launch --------------------------------------------------
extern "C" void kernel_launch(void* const* d_in, const int* in_sizes, int n_in,
                              void* d_out, int out_size)
{
    const float* batch = (const float*)d_in[0];
    const int*   lens  = (const int*)d_in[1];
    const int*   durs  = (const int*)d_in[3];
    const float* w1    = (const float*)d_in[4];
    const float* b1    = (const float*)d_in[5];
    const float* g1    = (const float*)d_in[6];
    const float* be1   = (const float*)d_in[7];
    const float* w2    = (const float*)d_in[8];
    const float* b2    = (const float*)d_in[9];
    const float* g2    = (const float*)d_in[10];
    const float* be2   = (const float*)d_in[11];
    const float* lw    = (const float*)d_in[12];
    const float* lb    = (const float*)d_in[13];

    float* out    = (float*)d_out;
    float* padded = out;
    float* mel    = out + (size_t)BB * LMAX * CC;
    float* pred   = mel + BB;

    __half *bufA, *buf1h, *wt;
    float  *buf1, *buf2;
    int    *cum;
    cudaGetSymbolAddress((void**)&bufA,  g_bufA);
    cudaGetSymbolAddress((void**)&buf1,  g_buf1);
    cudaGetSymbolAddress((void**)&buf1h, g_buf1h);
    cudaGetSymbolAddress((void**)&buf2,  g_buf2);
    cudaGetSymbolAddress((void**)&wt,    g_wt);
    cudaGetSymbolAddress((void**)&cum,   g_cum);
    __half* wt2 = wt + (size_t)KK * CC * CC;

    wt_kernel<<<(CC * CC + 255) / 256, 256>>>(w1, wt);
    wt_kernel<<<(CC * CC + 255) / 256, 256>>>(w2, wt2);
    dur_kernel<<<BB, 256>>>(durs, lens, cum, mel);
    round_kernel<<<(BT * (CC / 4)) / 256, 256>>>((const float4*)batch, bufA);

    dim3 gg(BT / BM, CC / BN);
    conv_mma_kernel<<<gg, 256>>>(bufA, wt, b1, buf1);
    ln_kernel<<<BT, 128>>>(buf1, g1, be1, buf1h);
    conv_mma_kernel<<<gg, 256>>>(buf1h, wt2, b2, buf2);
    ln_lin_kernel<<<BT, 128>>>(buf2, g2, be2, lw, lb, lens, pred);

    reg_kernel<<<dim3(LMAX / 32, BB), 256>>>(batch, cum, padded);
}

// round 10
// speedup vs baseline: 1.7869x; 1.0350x over previous
#include <cuda_runtime.h>
#include <cuda_fp16.h>
#include <cstdint>
#include <cstddef>

// Problem constants
#define BB   32
#define TT   1024
#define CC   512
#define KK   3
#define LMAX 4096
#define BT   (BB*TT)
#define LN_EPS 1e-5f

// GEMM tiling (fp16 mma.sync m16n8k16, fp32 accumulate)
#define BM 128
#define BN 128
#define BK 16
#define NSLAB ((KK*CC)/BK)    // 96
#define STG 3

// mega-kernel block partition
#define CONV_BLKS 1024        // (BT/BM) * (CC/BN) = 256*4
#define REG_BLKS  4096        // BB * (LMAX/32)
// pre-kernel block partition
#define RND_BLKS  16384       // BT*CC/4/256
#define WT_BLKS   1024        // CC*CC/256

// pair permutation within each 16-k group: pair t -> slot (t<4 ? 2t : 2(t-4)+1)
__host__ __device__ __forceinline__ int pslot(int t) {
    return (t < 4) ? 2 * t : 2 * (t - 4) + 1;
}

// ---------------- scratch (device globals; no allocations allowed) ----------
__device__ __half g_bufA[(size_t)BT * CC];         // fp16 pair-permuted batch
__device__ float  g_buf1[(size_t)BT * CC];         // conv1 out fp32
__device__ __half g_buf1h[(size_t)BT * CC];        // ln(conv1) fp16 pair-permuted
__device__ float  g_buf2[(size_t)BT * CC];         // conv2 out fp32
__device__ __half g_wt[2 * (size_t)KK * CC * CC];  // [set][k][ci/16][co][16perm]
__device__ int    g_cum[BB * TT];

// ================= helpers ==================================================
__device__ __forceinline__ uint32_t smem_u32(const void* p) {
    uint32_t r;
    asm("{ .reg .u64 t; cvta.to.shared.u64 t, %1; cvt.u32.u64 %0, t; }"
        : "=r"(r) : "l"(p));
    return r;
}
__device__ __forceinline__ void cp_async16(uint32_t dst, const void* src, bool ok) {
    int sz = ok ? 16 : 0;
    asm volatile("cp.async.ca.shared.global [%0], [%1], 16, %2;"
                 :: "r"(dst), "l"(src), "r"(sz));
}
#define CP_COMMIT() asm volatile("cp.async.commit_group;" ::: "memory")
#define CP_WAIT1()  asm volatile("cp.async.wait_group 1;" ::: "memory")

__device__ __forceinline__ void mma_f16(float* c, const uint32_t* a, const uint32_t* b) {
    asm volatile("mma.sync.aligned.m16n8k16.row.col.f32.f16.f16.f32 "
                 "{%0,%1,%2,%3}, {%4,%5,%6,%7}, {%8,%9}, {%0,%1,%2,%3};"
                 : "+f"(c[0]), "+f"(c[1]), "+f"(c[2]), "+f"(c[3])
                 : "r"(a[0]), "r"(a[1]), "r"(a[2]), "r"(a[3]),
                   "r"(b[0]), "r"(b[1]));
}

// write 4 consecutive logical values (w = within-group start, multiple of 4)
// into pair-permuted fp16 group storage.
__device__ __forceinline__ void store_perm4(__half* gbase, int w,
                                            float v0, float v1, float v2, float v3)
{
    int t0 = w >> 1;
    int s0 = pslot(t0);
    int s1 = pslot(t0 + 1);
    *(__half2*)(gbase + s0 * 2) = __floats2half2_rn(v0, v1);
    *(__half2*)(gbase + s1 * 2) = __floats2half2_rn(v2, v3);
}

// ============ PRE: round(batch->fp16 perm) | wt x2 | durations ==============
__global__ void __launch_bounds__(256) pre_kernel(const float4* __restrict__ batch4,
                                                  __half* __restrict__ bufA,
                                                  const float* __restrict__ w1,
                                                  const float* __restrict__ w2,
                                                  __half* __restrict__ wt1,
                                                  __half* __restrict__ wt2,
                                                  const int* __restrict__ durs,
                                                  const int* __restrict__ lens,
                                                  int* __restrict__ cum,
                                                  float* __restrict__ mel)
{
    __shared__ int sred[256];
    __shared__ int sscan[256];
    int bid = blockIdx.x;
    int tid = threadIdx.x;

    if (bid < RND_BLKS) {
        // ---- fp16 round + pair-permute copy ----
        size_t i = (size_t)bid * 256 + tid;            // over BT*CC/4
        float4 v = batch4[i];
        int f = (int)(i & 127);
        size_t rowbase = (i >> 7) * CC;
        int g = f >> 2;
        int w = (f & 3) * 4;
        store_perm4(bufA + rowbase + g * 16, w, v.x, v.y, v.z, v.w);
        return;
    }
    if (bid < RND_BLKS + 2 * WT_BLKS) {
        // ---- weight transform: w[co][ci][k] -> wt[k][ci/16][co][perm] ----
        int wb = bid - RND_BLKS;
        const float* w = (wb < WT_BLKS) ? w1 : w2;
        __half* wt = (wb < WT_BLKS) ? wt1 : wt2;
        int idx = (wb & (WT_BLKS - 1)) * 256 + tid;    // over CC*CC
        int co = idx >> 9;
        int ci = idx & (CC - 1);
        int g  = ci >> 4;
        int w16 = ci & 15;
        int pos = pslot(w16 >> 1) * 2 + (w16 & 1);
#pragma unroll
        for (int k = 0; k < KK; k++)
            wt[(((size_t)k * 32 + g) * CC + co) * 16 + pos] =
                __float2half_rn(w[((size_t)co * CC + ci) * KK + k]);
        return;
    }
    // ---- durations: mask, total==0 fallback, inclusive scan ----
    {
        int b   = bid - (RND_BLKS + 2 * WT_BLKS);
        int len = lens[b];
        int base = tid * 4;
        const int* drow = durs + (size_t)b * TT;

        int d[4];
#pragma unroll
        for (int j = 0; j < 4; j++)
            d[j] = (base + j < len) ? drow[base + j] : 0;
        int ls = d[0] + d[1] + d[2] + d[3];

        sred[tid] = ls;
        __syncthreads();
        for (int o = 128; o > 0; o >>= 1) {
            if (tid < o) sred[tid] += sred[tid + o];
            __syncthreads();
        }
        int total = sred[0];
        __syncthreads();

        if (total == 0) {
#pragma unroll
            for (int j = 0; j < 4; j++)
                d[j] = (base + j < len) ? 1 : 0;
            ls = d[0] + d[1] + d[2] + d[3];
        }

        sscan[tid] = ls;
        __syncthreads();
        for (int o = 1; o < 256; o <<= 1) {
            int v = (tid >= o) ? sscan[tid - o] : 0;
            __syncthreads();
            sscan[tid] += v;
            __syncthreads();
        }
        int c = sscan[tid] - ls;
#pragma unroll
        for (int j = 0; j < 4; j++) {
            c += d[j];
            cum[(size_t)b * TT + base + j] = c;
        }
        if (tid == 255) mel[b] = (float)c;
    }
}

// ============ MEGA: conv1 (blocks [0,1024)) | regulate (rest) ===============
__global__ void __launch_bounds__(256, 2) mega_kernel(const __half* __restrict__ A,
                                                      const __half* __restrict__ Wt,
                                                      const float* __restrict__ bias,
                                                      float* __restrict__ out,
                                                      const float* __restrict__ batch,
                                                      const int* __restrict__ cum,
                                                      float* __restrict__ padded)
{
    __shared__ __align__(16) __half As[STG][BM][16];
    __shared__ __align__(16) __half Bs[STG][BN][16];
    __shared__ int sc[TT];

    int tid  = threadIdx.x;

    if (blockIdx.x < CONV_BLKS) {
        // ================= conv tile =================
        int wid  = tid >> 5;
        int lane = tid & 31;
        int warp_m = wid & 1;
        int warp_n = wid >> 1;
        int gid = lane >> 2;
        int tig = lane & 3;

        int m0 = (blockIdx.x >> 2) * BM;
        int b  = m0 >> 10;
        int t0 = m0 & 1023;
        int n0 = (blockIdx.x & 3) * BN;
        const __half* Ab = A + (size_t)b * TT * CC;

        int lrow  = tid >> 1;
        int lhalf = tid & 1;

        float c[4][4][4];
#pragma unroll
        for (int mt = 0; mt < 4; mt++)
#pragma unroll
            for (int nt = 0; nt < 4; nt++)
#pragma unroll
                for (int q = 0; q < 4; q++) c[mt][nt][q] = 0.f;

        auto load_slab = [&](int s, int st) {
            int k  = s >> 5;
            int gI = s & 31;
            int strow = t0 + lrow + k - 1;
            bool ok = (strow >= 0 && strow < TT);
            const __half* asrc = Ab + (ok ? (size_t)strow * CC : 0) + gI * 16 + lhalf * 8;
            cp_async16(smem_u32(&As[st][lrow][lhalf * 8]), asrc, ok);
            const __half* bsrc = Wt + (((size_t)k * 32 + gI) * CC + n0 + lrow) * 16 + lhalf * 8;
            cp_async16(smem_u32(&Bs[st][lrow][lhalf * 8]), bsrc, true);
        };

        load_slab(0, 0); CP_COMMIT();
        load_slab(1, 1); CP_COMMIT();

        for (int s = 0; s < NSLAB; s++) {
            int st = s % STG;
            CP_WAIT1();
            __syncthreads();
            if (s + 2 < NSLAB) load_slab(s + 2, (s + 2) % STG);
            CP_COMMIT();

            uint32_t af[4][4];
#pragma unroll
            for (int mt = 0; mt < 4; mt++) {
                int mr = warp_m * 64 + mt * 16;
                uint2 lo = *(const uint2*)&As[st][mr + gid    ][tig * 4];
                uint2 hi = *(const uint2*)&As[st][mr + gid + 8][tig * 4];
                af[mt][0] = lo.x;
                af[mt][2] = lo.y;
                af[mt][1] = hi.x;
                af[mt][3] = hi.y;
            }
            uint32_t bf[4][2];
#pragma unroll
            for (int nt = 0; nt < 4; nt++) {
                int nc = warp_n * 32 + nt * 8 + gid;
                uint2 r = *(const uint2*)&Bs[st][nc][tig * 4];
                bf[nt][0] = r.x;
                bf[nt][1] = r.y;
            }
#pragma unroll
            for (int mt = 0; mt < 4; mt++)
#pragma unroll
                for (int nt = 0; nt < 4; nt++)
                    mma_f16(c[mt][nt], af[mt], bf[nt]);
        }

#pragma unroll
        for (int mt = 0; mt < 4; mt++) {
            int row = m0 + warp_m * 64 + mt * 16 + gid;
#pragma unroll
            for (int nt = 0; nt < 4; nt++) {
                int col = n0 + warp_n * 32 + nt * 8 + tig * 2;
                float b0 = __ldg(&bias[col]);
                float b1 = __ldg(&bias[col + 1]);
                float2 v0, v1;
                v0.x = fmaxf(c[mt][nt][0] + b0, 0.f);
                v0.y = fmaxf(c[mt][nt][1] + b1, 0.f);
                v1.x = fmaxf(c[mt][nt][2] + b0, 0.f);
                v1.y = fmaxf(c[mt][nt][3] + b1, 0.f);
                *(float2*)&out[(size_t)row * CC + col]       = v0;
                *(float2*)&out[(size_t)(row + 8) * CC + col] = v1;
            }
        }
    } else {
        // ================= regulate =================
        int r  = blockIdx.x - CONV_BLKS;
        int b  = r >> 7;
        int f0 = (r & 127) * 32;
        const int* crow = cum + (size_t)b * TT;
#pragma unroll
        for (int j = 0; j < 4; j++) sc[tid + 256 * j] = crow[tid + 256 * j];
        __syncthreads();
        int total = sc[TT - 1];
        int warp = tid >> 5, lane = tid & 31;
        float* outb = padded + (size_t)b * LMAX * CC;
        const float* inb = batch + (size_t)b * TT * CC;
#pragma unroll
        for (int qq = 0; qq < 4; qq++) {
            int f = f0 + warp * 4 + qq;
            float4* dst = (float4*)(outb + (size_t)f * CC);
            if (f < total) {
                int lo = 0, hi = TT;
                while (lo < hi) {
                    int mid = (lo + hi) >> 1;
                    if (sc[mid] <= f) lo = mid + 1; else hi = mid;
                }
                const float4* src = (const float4*)(inb + (size_t)lo * CC);
#pragma unroll
                for (int u = 0; u < 4; u++) dst[lane + 32 * u] = src[lane + 32 * u];
            } else {
                float4 z = make_float4(0.f, 0.f, 0.f, 0.f);
#pragma unroll
                for (int u = 0; u < 4; u++) dst[lane + 32 * u] = z;
            }
        }
    }
}

// ---------------- conv2: plain conv-as-GEMM on fp16 mma.sync ----------------
__global__ void __launch_bounds__(256, 2) conv_mma_kernel(const __half* __restrict__ A,
                                                          const __half* __restrict__ Wt,
                                                          const float* __restrict__ bias,
                                                          float* __restrict__ out)
{
    __shared__ __align__(16) __half As[STG][BM][16];
    __shared__ __align__(16) __half Bs[STG][BN][16];

    int tid  = threadIdx.x;
    int wid  = tid >> 5;
    int lane = tid & 31;
    int warp_m = wid & 1;
    int warp_n = wid >> 1;
    int gid = lane >> 2;
    int tig = lane & 3;

    int m0 = blockIdx.x * BM;
    int b  = m0 >> 10;
    int t0 = m0 & 1023;
    int n0 = blockIdx.y * BN;
    const __half* Ab = A + (size_t)b * TT * CC;

    int lrow  = tid >> 1;
    int lhalf = tid & 1;

    float c[4][4][4];
#pragma unroll
    for (int mt = 0; mt < 4; mt++)
#pragma unroll
        for (int nt = 0; nt < 4; nt++)
#pragma unroll
            for (int q = 0; q < 4; q++) c[mt][nt][q] = 0.f;

    auto load_slab = [&](int s, int st) {
        int k  = s >> 5;
        int gI = s & 31;
        int strow = t0 + lrow + k - 1;
        bool ok = (strow >= 0 && strow < TT);
        const __half* asrc = Ab + (ok ? (size_t)strow * CC : 0) + gI * 16 + lhalf * 8;
        cp_async16(smem_u32(&As[st][lrow][lhalf * 8]), asrc, ok);
        const __half* bsrc = Wt + (((size_t)k * 32 + gI) * CC + n0 + lrow) * 16 + lhalf * 8;
        cp_async16(smem_u32(&Bs[st][lrow][lhalf * 8]), bsrc, true);
    };

    load_slab(0, 0); CP_COMMIT();
    load_slab(1, 1); CP_COMMIT();

    for (int s = 0; s < NSLAB; s++) {
        int st = s % STG;
        CP_WAIT1();
        __syncthreads();
        if (s + 2 < NSLAB) load_slab(s + 2, (s + 2) % STG);
        CP_COMMIT();

        uint32_t af[4][4];
#pragma unroll
        for (int mt = 0; mt < 4; mt++) {
            int mr = warp_m * 64 + mt * 16;
            uint2 lo = *(const uint2*)&As[st][mr + gid    ][tig * 4];
            uint2 hi = *(const uint2*)&As[st][mr + gid + 8][tig * 4];
            af[mt][0] = lo.x;
            af[mt][2] = lo.y;
            af[mt][1] = hi.x;
            af[mt][3] = hi.y;
        }
        uint32_t bf[4][2];
#pragma unroll
        for (int nt = 0; nt < 4; nt++) {
            int nc = warp_n * 32 + nt * 8 + gid;
            uint2 r = *(const uint2*)&Bs[st][nc][tig * 4];
            bf[nt][0] = r.x;
            bf[nt][1] = r.y;
        }
#pragma unroll
        for (int mt = 0; mt < 4; mt++)
#pragma unroll
            for (int nt = 0; nt < 4; nt++)
                mma_f16(c[mt][nt], af[mt], bf[nt]);
    }

#pragma unroll
    for (int mt = 0; mt < 4; mt++) {
        int row = m0 + warp_m * 64 + mt * 16 + gid;
#pragma unroll
        for (int nt = 0; nt < 4; nt++) {
            int col = n0 + warp_n * 32 + nt * 8 + tig * 2;
            float b0 = __ldg(&bias[col]);
            float b1 = __ldg(&bias[col + 1]);
            float2 v0, v1;
            v0.x = fmaxf(c[mt][nt][0] + b0, 0.f);
            v0.y = fmaxf(c[mt][nt][1] + b1, 0.f);
            v1.x = fmaxf(c[mt][nt][2] + b0, 0.f);
            v1.y = fmaxf(c[mt][nt][3] + b1, 0.f);
            *(float2*)&out[(size_t)row * CC + col]       = v0;
            *(float2*)&out[(size_t)(row + 8) * CC + col] = v1;
        }
    }
}

// ---------------- LayerNorm over C=512, one block per row -------------------
// Reads fp32 normal order, writes fp16 pair-permuted (input to conv2).
__global__ void __launch_bounds__(128) ln_kernel(const float* __restrict__ x,
                                                 const float* __restrict__ g,
                                                 const float* __restrict__ beta,
                                                 __half* __restrict__ xo)
{
    size_t row = blockIdx.x;
    const float4* xr = (const float4*)(x + row * CC);
    int tid = threadIdx.x;
    float4 v = xr[tid];
    float s = v.x + v.y + v.z + v.w;
    float q = v.x * v.x + v.y * v.y + v.z * v.z + v.w * v.w;
#pragma unroll
    for (int o = 16; o > 0; o >>= 1) {
        s += __shfl_xor_sync(0xffffffffu, s, o);
        q += __shfl_xor_sync(0xffffffffu, q, o);
    }
    __shared__ float ss[4], sq[4];
    int w = tid >> 5, l = tid & 31;
    if (l == 0) { ss[w] = s; sq[w] = q; }
    __syncthreads();
    s = ss[0] + ss[1] + ss[2] + ss[3];
    q = sq[0] + sq[1] + sq[2] + sq[3];
    float mean = s * (1.f / CC);
    float var  = q * (1.f / CC) - mean * mean;
    float r = rsqrtf(var + LN_EPS);
    float4 gv = ((const float4*)g)[tid];
    float4 bv = ((const float4*)beta)[tid];
    float o0 = (v.x - mean) * r * gv.x + bv.x;
    float o1 = (v.y - mean) * r * gv.y + bv.y;
    float o2 = (v.z - mean) * r * gv.z + bv.z;
    float o3 = (v.w - mean) * r * gv.w + bv.w;
    int grp = tid >> 2;
    int wof = (tid & 3) * 4;
    store_perm4(xo + row * CC + grp * 16, wof, o0, o1, o2, o3);
}

// ---------------- LN + Linear(C->1) + mask, one block per row ---------------
__global__ void __launch_bounds__(128) ln_lin_kernel(const float* __restrict__ x,
                                                     const float* __restrict__ g,
                                                     const float* __restrict__ beta,
                                                     const float* __restrict__ lw,
                                                     const float* __restrict__ lb,
                                                     const int* __restrict__ lens,
                                                     float* __restrict__ pred)
{
    size_t row = blockIdx.x;
    const float4* xr = (const float4*)(x + row * CC);
    int tid = threadIdx.x;
    float4 v = xr[tid];
    float s = v.x + v.y + v.z + v.w;
    float q = v.x * v.x + v.y * v.y + v.z * v.z + v.w * v.w;
#pragma unroll
    for (int o = 16; o > 0; o >>= 1) {
        s += __shfl_xor_sync(0xffffffffu, s, o);
        q += __shfl_xor_sync(0xffffffffu, q, o);
    }
    __shared__ float ss[4], sq[4], sp[4];
    int w = tid >> 5, l = tid & 31;
    if (l == 0) { ss[w] = s; sq[w] = q; }
    __syncthreads();
    s = ss[0] + ss[1] + ss[2] + ss[3];
    q = sq[0] + sq[1] + sq[2] + sq[3];
    float mean = s * (1.f / CC);
    float var  = q * (1.f / CC) - mean * mean;
    float r = rsqrtf(var + LN_EPS);
    float4 gv = ((const float4*)g)[tid];
    float4 bv = ((const float4*)beta)[tid];
    float4 wv = ((const float4*)lw)[tid];
    float part = ((v.x - mean) * r * gv.x + bv.x) * wv.x
               + ((v.y - mean) * r * gv.y + bv.y) * wv.y
               + ((v.z - mean) * r * gv.z + bv.z) * wv.z
               + ((v.w - mean) * r * gv.w + bv.w) * wv.w;
#pragma unroll
    for (int o = 16; o > 0; o >>= 1)
        part += __shfl_xor_sync(0xffffffffu, part, o);
    if (l == 0) sp[w] = part;
    __syncthreads();
    if (tid == 0) {
        float val = sp[0] + sp[1] + sp[2] + sp[3] + lb[0];
        int b = (int)(row >> 10);
        int t = (int)(row & 1023);
        pred[row] = (t < lens[b]) ? val : 0.f;
    }
}

// ---------------- launch --------------------------------------------------
extern "C" void kernel_launch(void* const* d_in, const int* in_sizes, int n_in,
                              void* d_out, int out_size)
{
    const float* batch = (const float*)d_in[0];
    const int*   lens  = (const int*)d_in[1];
    const int*   durs  = (const int*)d_in[3];
    const float* w1    = (const float*)d_in[4];
    const float* b1    = (const float*)d_in[5];
    const float* g1    = (const float*)d_in[6];
    const float* be1   = (const float*)d_in[7];
    const float* w2    = (const float*)d_in[8];
    const float* b2    = (const float*)d_in[9];
    const float* g2    = (const float*)d_in[10];
    const float* be2   = (const float*)d_in[11];
    const float* lw    = (const float*)d_in[12];
    const float* lb    = (const float*)d_in[13];

    float* out    = (float*)d_out;
    float* padded = out;
    float* mel    = out + (size_t)BB * LMAX * CC;
    float* pred   = mel + BB;

    __half *bufA, *buf1h, *wt;
    float  *buf1, *buf2;
    int    *cum;
    cudaGetSymbolAddress((void**)&bufA,  g_bufA);
    cudaGetSymbolAddress((void**)&buf1,  g_buf1);
    cudaGetSymbolAddress((void**)&buf1h, g_buf1h);
    cudaGetSymbolAddress((void**)&buf2,  g_buf2);
    cudaGetSymbolAddress((void**)&wt,    g_wt);
    cudaGetSymbolAddress((void**)&cum,   g_cum);
    __half* wt2 = wt + (size_t)KK * CC * CC;

    // round | wt1 | wt2 | durations — all independent, one launch
    pre_kernel<<<RND_BLKS + 2 * WT_BLKS + BB, 256>>>(
        (const float4*)batch, bufA, w1, w2, wt, wt2, durs, lens, cum, mel);

    // conv1 (tensor-bound) overlapped with regulate (DRAM-bound)
    mega_kernel<<<CONV_BLKS + REG_BLKS, 256>>>(
        bufA, wt, b1, buf1, batch, cum, padded);

    ln_kernel<<<BT, 128>>>(buf1, g1, be1, buf1h);
    conv_mma_kernel<<<dim3(BT / BM, CC / BN), 256>>>(buf1h, wt2, b2, buf2);
    ln_lin_kernel<<<BT, 128>>>(buf2, g2, be2, lw, lb, lens, pred);
}

// round 11
// speedup vs baseline: 1.8671x; 1.0449x over previous
#include <cuda_runtime.h>
#include <cuda_fp16.h>
#include <cstdint>
#include <cstddef>

// Problem constants
#define BB   32
#define TT   1024
#define CC   512
#define KK   3
#define LMAX 4096
#define BT   (BB*TT)
#define LN_EPS 1e-5f

// GEMM tiling (fp16 mma.sync m16n8k16, fp32 accumulate)
#define BM 128
#define BN 128
#define BK 32
#define NSLAB ((KK*CC)/BK)    // 48
#define STG 3

// mega-kernel block partition
#define CONV_BLKS 1024        // (BT/BM) * (CC/BN)
#define REG_BLKS  4096        // BB * (LMAX/32)
// pre-kernel block partition
#define RND_BLKS  16384       // BT*CC/4/256
#define WT_BLKS   1024        // CC*CC/256

// pair permutation within each 16-k group: pair t -> slot (t<4 ? 2t : 2(t-4)+1)
__host__ __device__ __forceinline__ int pslot(int t) {
    return (t < 4) ? 2 * t : 2 * (t - 4) + 1;
}

// ---------------- scratch (device globals; no allocations allowed) ----------
__device__ __half g_bufA[(size_t)BT * CC];         // fp16 pair-permuted batch
__device__ float  g_buf1[(size_t)BT * CC];         // conv1 out fp32
__device__ __half g_buf1h[(size_t)BT * CC];        // ln(conv1) fp16 pair-permuted
__device__ float  g_buf2[(size_t)BT * CC];         // conv2 out fp32
__device__ __half g_wt[2 * (size_t)KK * CC * CC];  // [set][k][ci/16][co][16perm]
__device__ int    g_cum[BB * TT];

// ================= helpers ==================================================
__device__ __forceinline__ uint32_t smem_u32(const void* p) {
    uint32_t r;
    asm("{ .reg .u64 t; cvta.to.shared.u64 t, %1; cvt.u32.u64 %0, t; }"
        : "=r"(r) : "l"(p));
    return r;
}
__device__ __forceinline__ void cp_async16(uint32_t dst, const void* src, bool ok) {
    int sz = ok ? 16 : 0;
    asm volatile("cp.async.ca.shared.global [%0], [%1], 16, %2;"
                 :: "r"(dst), "l"(src), "r"(sz));
}
#define CP_COMMIT() asm volatile("cp.async.commit_group;" ::: "memory")
#define CP_WAIT1()  asm volatile("cp.async.wait_group 1;" ::: "memory")

__device__ __forceinline__ void mma_f16(float* c, const uint32_t* a, const uint32_t* b) {
    asm volatile("mma.sync.aligned.m16n8k16.row.col.f32.f16.f16.f32 "
                 "{%0,%1,%2,%3}, {%4,%5,%6,%7}, {%8,%9}, {%0,%1,%2,%3};"
                 : "+f"(c[0]), "+f"(c[1]), "+f"(c[2]), "+f"(c[3])
                 : "r"(a[0]), "r"(a[1]), "r"(a[2]), "r"(a[3]),
                   "r"(b[0]), "r"(b[1]));
}

// write 4 consecutive logical values into pair-permuted fp16 group storage.
__device__ __forceinline__ void store_perm4(__half* gbase, int w,
                                            float v0, float v1, float v2, float v3)
{
    int t0 = w >> 1;
    int s0 = pslot(t0);
    int s1 = pslot(t0 + 1);
    *(__half2*)(gbase + s0 * 2) = __floats2half2_rn(v0, v1);
    *(__half2*)(gbase + s1 * 2) = __floats2half2_rn(v2, v3);
}

// ============ PRE: round(batch->fp16 perm) | wt x2 | durations ==============
__global__ void __launch_bounds__(256) pre_kernel(const float4* __restrict__ batch4,
                                                  __half* __restrict__ bufA,
                                                  const float* __restrict__ w1,
                                                  const float* __restrict__ w2,
                                                  __half* __restrict__ wt1,
                                                  __half* __restrict__ wt2,
                                                  const int* __restrict__ durs,
                                                  const int* __restrict__ lens,
                                                  int* __restrict__ cum,
                                                  float* __restrict__ mel)
{
    __shared__ int sred[256];
    __shared__ int sscan[256];
    int bid = blockIdx.x;
    int tid = threadIdx.x;

    if (bid < RND_BLKS) {
        size_t i = (size_t)bid * 256 + tid;
        float4 v = batch4[i];
        int f = (int)(i & 127);
        size_t rowbase = (i >> 7) * CC;
        int g = f >> 2;
        int w = (f & 3) * 4;
        store_perm4(bufA + rowbase + g * 16, w, v.x, v.y, v.z, v.w);
        return;
    }
    if (bid < RND_BLKS + 2 * WT_BLKS) {
        int wb = bid - RND_BLKS;
        const float* w = (wb < WT_BLKS) ? w1 : w2;
        __half* wt = (wb < WT_BLKS) ? wt1 : wt2;
        int idx = (wb & (WT_BLKS - 1)) * 256 + tid;
        int co = idx >> 9;
        int ci = idx & (CC - 1);
        int g  = ci >> 4;
        int w16 = ci & 15;
        int pos = pslot(w16 >> 1) * 2 + (w16 & 1);
#pragma unroll
        for (int k = 0; k < KK; k++)
            wt[(((size_t)k * 32 + g) * CC + co) * 16 + pos] =
                __float2half_rn(w[((size_t)co * CC + ci) * KK + k]);
        return;
    }
    {
        int b   = bid - (RND_BLKS + 2 * WT_BLKS);
        int len = lens[b];
        int base = tid * 4;
        const int* drow = durs + (size_t)b * TT;

        int d[4];
#pragma unroll
        for (int j = 0; j < 4; j++)
            d[j] = (base + j < len) ? drow[base + j] : 0;
        int ls = d[0] + d[1] + d[2] + d[3];

        sred[tid] = ls;
        __syncthreads();
        for (int o = 128; o > 0; o >>= 1) {
            if (tid < o) sred[tid] += sred[tid + o];
            __syncthreads();
        }
        int total = sred[0];
        __syncthreads();

        if (total == 0) {
#pragma unroll
            for (int j = 0; j < 4; j++)
                d[j] = (base + j < len) ? 1 : 0;
            ls = d[0] + d[1] + d[2] + d[3];
        }

        sscan[tid] = ls;
        __syncthreads();
        for (int o = 1; o < 256; o <<= 1) {
            int v = (tid >= o) ? sscan[tid - o] : 0;
            __syncthreads();
            sscan[tid] += v;
            __syncthreads();
        }
        int c = sscan[tid] - ls;
#pragma unroll
        for (int j = 0; j < 4; j++) {
            c += d[j];
            cum[(size_t)b * TT + base + j] = c;
        }
        if (tid == 255) mel[b] = (float)c;
    }
}

// ======= conv tile body (BK=32, XOR-swizzled smem, 1 barrier/slab) ==========
// smem rows are 64B; 8B-chunk j of row r stored at j ^ ((r&2)<<1).
struct ConvSmem {
    __half As[STG][BM][BK];
    __half Bs[STG][BN][BK];
};

__device__ __forceinline__ void conv_tile(ConvSmem* sm,
                                          const __half* __restrict__ A,
                                          const __half* __restrict__ Wt,
                                          const float* __restrict__ bias,
                                          float* __restrict__ out,
                                          int m0, int n0)
{
    int tid  = threadIdx.x;
    int wid  = tid >> 5;
    int lane = tid & 31;
    int warp_m = wid & 1;
    int warp_n = wid >> 1;
    int gid = lane >> 2;
    int tig = lane & 3;
    int msk = (gid & 2) << 1;          // 8B-chunk xor mask for frag reads

    int b  = m0 >> 10;
    int t0 = m0 & 1023;
    const __half* Ab = A + (size_t)b * TT * CC;

    float c[4][4][4];
#pragma unroll
    for (int mt = 0; mt < 4; mt++)
#pragma unroll
        for (int nt = 0; nt < 4; nt++)
#pragma unroll
            for (int q = 0; q < 4; q++) c[mt][nt][q] = 0.f;

    auto load_slab = [&](int s, int st) {
        int k  = s >> 4;               // conv tap 0..2 (16 slabs per tap)
        int gI = (s & 15) * 2;         // first 16-group of this slab
#pragma unroll
        for (int h = 0; h < 2; h++) {
            int idx = tid + h * 256;   // 0..511
            int row = idx >> 2;
            int q   = idx & 3;         // 16B chunk
            int dq  = q ^ (row & 2);   // swizzled 16B chunk
            int strow = t0 + row + k - 1;
            bool ok = (strow >= 0 && strow < TT);
            const __half* asrc = Ab + (ok ? (size_t)strow * CC : 0) + gI * 16 + q * 8;
            cp_async16(smem_u32(&sm->As[st][row][dq * 8]), asrc, ok);
            const __half* bsrc = Wt + (((size_t)k * 32 + gI + (q >> 1)) * CC + n0 + row) * 16
                                 + (q & 1) * 8;
            cp_async16(smem_u32(&sm->Bs[st][row][dq * 8]), bsrc, true);
        }
    };

    load_slab(0, 0); CP_COMMIT();
    load_slab(1, 1); CP_COMMIT();

    for (int s = 0; s < NSLAB; s++) {
        int st = s % STG;
        CP_WAIT1();
        __syncthreads();
        if (s + 2 < NSLAB) load_slab(s + 2, (s + 2) % STG);
        CP_COMMIT();

#pragma unroll
        for (int g = 0; g < 2; g++) {
            int cw = ((g * 4 + tig) ^ msk) * 4;    // halves offset of 8B frag chunk
            uint32_t af[4][4];
#pragma unroll
            for (int mt = 0; mt < 4; mt++) {
                int mr = warp_m * 64 + mt * 16;
                uint2 lo = *(const uint2*)&sm->As[st][mr + gid    ][cw];
                uint2 hi = *(const uint2*)&sm->As[st][mr + gid + 8][cw];
                af[mt][0] = lo.x;
                af[mt][2] = lo.y;
                af[mt][1] = hi.x;
                af[mt][3] = hi.y;
            }
            uint32_t bf[4][2];
#pragma unroll
            for (int nt = 0; nt < 4; nt++) {
                int nc = warp_n * 32 + nt * 8 + gid;
                uint2 r = *(const uint2*)&sm->Bs[st][nc][cw];
                bf[nt][0] = r.x;
                bf[nt][1] = r.y;
            }
#pragma unroll
            for (int mt = 0; mt < 4; mt++)
#pragma unroll
                for (int nt = 0; nt < 4; nt++)
                    mma_f16(c[mt][nt], af[mt], bf[nt]);
        }
    }

    // epilogue: bias + relu, coalesced stores
#pragma unroll
    for (int mt = 0; mt < 4; mt++) {
        int row = m0 + warp_m * 64 + mt * 16 + gid;
#pragma unroll
        for (int nt = 0; nt < 4; nt++) {
            int col = n0 + warp_n * 32 + nt * 8 + tig * 2;
            float b0 = __ldg(&bias[col]);
            float b1 = __ldg(&bias[col + 1]);
            float2 v0, v1;
            v0.x = fmaxf(c[mt][nt][0] + b0, 0.f);
            v0.y = fmaxf(c[mt][nt][1] + b1, 0.f);
            v1.x = fmaxf(c[mt][nt][2] + b0, 0.f);
            v1.y = fmaxf(c[mt][nt][3] + b1, 0.f);
            *(float2*)&out[(size_t)row * CC + col]       = v0;
            *(float2*)&out[(size_t)(row + 8) * CC + col] = v1;
        }
    }
}

// ============ MEGA: conv1 (blocks [0,1024)) | regulate (rest) ===============
__global__ void __launch_bounds__(256, 2) mega_kernel(const __half* __restrict__ A,
                                                      const __half* __restrict__ Wt,
                                                      const float* __restrict__ bias,
                                                      float* __restrict__ out,
                                                      const float* __restrict__ batch,
                                                      const int* __restrict__ cum,
                                                      float* __restrict__ padded)
{
    __shared__ ConvSmem sm;            // 48KB; sc aliases it in the reg branch
    int tid = threadIdx.x;

    if (blockIdx.x < CONV_BLKS) {
        int m0 = (blockIdx.x >> 2) * BM;
        int n0 = (blockIdx.x & 3) * BN;
        conv_tile(&sm, A, Wt, bias, out, m0, n0);
    } else {
        int* sc = (int*)&sm;           // 4KB overlay (disjoint branch)
        int r  = blockIdx.x - CONV_BLKS;
        int b  = r >> 7;
        int f0 = (r & 127) * 32;
        const int* crow = cum + (size_t)b * TT;
#pragma unroll
        for (int j = 0; j < 4; j++) sc[tid + 256 * j] = crow[tid + 256 * j];
        __syncthreads();
        int total = sc[TT - 1];
        int warp = tid >> 5, lane = tid & 31;
        float* outb = padded + (size_t)b * LMAX * CC;
        const float* inb = batch + (size_t)b * TT * CC;
#pragma unroll
        for (int qq = 0; qq < 4; qq++) {
            int f = f0 + warp * 4 + qq;
            float4* dst = (float4*)(outb + (size_t)f * CC);
            if (f < total) {
                int lo = 0, hi = TT;
                while (lo < hi) {
                    int mid = (lo + hi) >> 1;
                    if (sc[mid] <= f) lo = mid + 1; else hi = mid;
                }
                const float4* src = (const float4*)(inb + (size_t)lo * CC);
#pragma unroll
                for (int u = 0; u < 4; u++) dst[lane + 32 * u] = src[lane + 32 * u];
            } else {
                float4 z = make_float4(0.f, 0.f, 0.f, 0.f);
#pragma unroll
                for (int u = 0; u < 4; u++) dst[lane + 32 * u] = z;
            }
        }
    }
}

// ---------------- conv2: plain conv-as-GEMM ---------------------------------
__global__ void __launch_bounds__(256, 2) conv_mma_kernel(const __half* __restrict__ A,
                                                          const __half* __restrict__ Wt,
                                                          const float* __restrict__ bias,
                                                          float* __restrict__ out)
{
    __shared__ ConvSmem sm;
    conv_tile(&sm, A, Wt, bias, out, blockIdx.x * BM, blockIdx.y * BN);
}

// ---------------- LayerNorm over C=512, one block per row -------------------
__global__ void __launch_bounds__(128) ln_kernel(const float* __restrict__ x,
                                                 const float* __restrict__ g,
                                                 const float* __restrict__ beta,
                                                 __half* __restrict__ xo)
{
    size_t row = blockIdx.x;
    const float4* xr = (const float4*)(x + row * CC);
    int tid = threadIdx.x;
    float4 v = xr[tid];
    float s = v.x + v.y + v.z + v.w;
    float q = v.x * v.x + v.y * v.y + v.z * v.z + v.w * v.w;
#pragma unroll
    for (int o = 16; o > 0; o >>= 1) {
        s += __shfl_xor_sync(0xffffffffu, s, o);
        q += __shfl_xor_sync(0xffffffffu, q, o);
    }
    __shared__ float ss[4], sq[4];
    int w = tid >> 5, l = tid & 31;
    if (l == 0) { ss[w] = s; sq[w] = q; }
    __syncthreads();
    s = ss[0] + ss[1] + ss[2] + ss[3];
    q = sq[0] + sq[1] + sq[2] + sq[3];
    float mean = s * (1.f / CC);
    float var  = q * (1.f / CC) - mean * mean;
    float r = rsqrtf(var + LN_EPS);
    float4 gv = ((const float4*)g)[tid];
    float4 bv = ((const float4*)beta)[tid];
    float o0 = (v.x - mean) * r * gv.x + bv.x;
    float o1 = (v.y - mean) * r * gv.y + bv.y;
    float o2 = (v.z - mean) * r * gv.z + bv.z;
    float o3 = (v.w - mean) * r * gv.w + bv.w;
    int grp = tid >> 2;
    int wof = (tid & 3) * 4;
    store_perm4(xo + row * CC + grp * 16, wof, o0, o1, o2, o3);
}

// ---------------- LN + Linear(C->1) + mask, one block per row ---------------
__global__ void __launch_bounds__(128) ln_lin_kernel(const float* __restrict__ x,
                                                     const float* __restrict__ g,
                                                     const float* __restrict__ beta,
                                                     const float* __restrict__ lw,
                                                     const float* __restrict__ lb,
                                                     const int* __restrict__ lens,
                                                     float* __restrict__ pred)
{
    size_t row = blockIdx.x;
    const float4* xr = (const float4*)(x + row * CC);
    int tid = threadIdx.x;
    float4 v = xr[tid];
    float s = v.x + v.y + v.z + v.w;
    float q = v.x * v.x + v.y * v.y + v.z * v.z + v.w * v.w;
#pragma unroll
    for (int o = 16; o > 0; o >>= 1) {
        s += __shfl_xor_sync(0xffffffffu, s, o);
        q += __shfl_xor_sync(0xffffffffu, q, o);
    }
    __shared__ float ss[4], sq[4], sp[4];
    int w = tid >> 5, l = tid & 31;
    if (l == 0) { ss[w] = s; sq[w] = q; }
    __syncthreads();
    s = ss[0] + ss[1] + ss[2] + ss[3];
    q = sq[0] + sq[1] + sq[2] + sq[3];
    float mean = s * (1.f / CC);
    float var  = q * (1.f / CC) - mean * mean;
    float r = rsqrtf(var + LN_EPS);
    float4 gv = ((const float4*)g)[tid];
    float4 bv = ((const float4*)beta)[tid];
    float4 wv = ((const float4*)lw)[tid];
    float part = ((v.x - mean) * r * gv.x + bv.x) * wv.x
               + ((v.y - mean) * r * gv.y + bv.y) * wv.y
               + ((v.z - mean) * r * gv.z + bv.z) * wv.z
               + ((v.w - mean) * r * gv.w + bv.w) * wv.w;
#pragma unroll
    for (int o = 16; o > 0; o >>= 1)
        part += __shfl_xor_sync(0xffffffffu, part, o);
    if (l == 0) sp[w] = part;
    __syncthreads();
    if (tid == 0) {
        float val = sp[0] + sp[1] + sp[2] + sp[3] + lb[0];
        int b = (int)(row >> 10);
        int t = (int)(row & 1023);
        pred[row] = (t < lens[b]) ? val : 0.f;
    }
}

// ---------------- launch --------------------------------------------------
extern "C" void kernel_launch(void* const* d_in, const int* in_sizes, int n_in,
                              void* d_out, int out_size)
{
    const float* batch = (const float*)d_in[0];
    const int*   lens  = (const int*)d_in[1];
    const int*   durs  = (const int*)d_in[3];
    const float* w1    = (const float*)d_in[4];
    const float* b1    = (const float*)d_in[5];
    const float* g1    = (const float*)d_in[6];
    const float* be1   = (const float*)d_in[7];
    const float* w2    = (const float*)d_in[8];
    const float* b2    = (const float*)d_in[9];
    const float* g2    = (const float*)d_in[10];
    const float* be2   = (const float*)d_in[11];
    const float* lw    = (const float*)d_in[12];
    const float* lb    = (const float*)d_in[13];

    float* out    = (float*)d_out;
    float* padded = out;
    float* mel    = out + (size_t)BB * LMAX * CC;
    float* pred   = mel + BB;

    __half *bufA, *buf1h, *wt;
    float  *buf1, *buf2;
    int    *cum;
    cudaGetSymbolAddress((void**)&bufA,  g_bufA);
    cudaGetSymbolAddress((void**)&buf1,  g_buf1);
    cudaGetSymbolAddress((void**)&buf1h, g_buf1h);
    cudaGetSymbolAddress((void**)&buf2,  g_buf2);
    cudaGetSymbolAddress((void**)&wt,    g_wt);
    cudaGetSymbolAddress((void**)&cum,   g_cum);
    __half* wt2 = wt + (size_t)KK * CC * CC;

    pre_kernel<<<RND_BLKS + 2 * WT_BLKS + BB, 256>>>(
        (const float4*)batch, bufA, w1, w2, wt, wt2, durs, lens, cum, mel);

    mega_kernel<<<CONV_BLKS + REG_BLKS, 256>>>(
        bufA, wt, b1, buf1, batch, cum, padded);

    ln_kernel<<<BT, 128>>>(buf1, g1, be1, buf1h);
    conv_mma_kernel<<<dim3(BT / BM, CC / BN), 256>>>(buf1h, wt2, b2, buf2);
    ln_lin_kernel<<<BT, 128>>>(buf2, g2, be2, lw, lb, lens, pred);
}